// round 1
// baseline (speedup 1.0000x reference)
#include <cuda_runtime.h>
#include <math_constants.h>

// Problem constants
#define B_   4
#define N_   2048
#define DIM_ 1024
#define H_   16
#define HD_  64
#define QKV_STRIDE 3072   // 3*DIM
#define SCALE_ 0.125f     // 1/sqrt(64)

// Scratch for the QKV projection: [B*N, 3*DIM] = 8192 x 3072 fp32 = 96 MB.
__device__ float g_qkv[(size_t)B_ * N_ * QKV_STRIDE];

// ---------------------------------------------------------------------------
// Kernel 1: QKV projection.  C[m,e] = sum_k x[m,k] * w[e,k] + bias[e]
// M=8192, N=3072, K=1024.  128x128 block tile, BK=8, 256 threads, 8x8/thread.
// Double-buffered smem.
// ---------------------------------------------------------------------------
__global__ __launch_bounds__(256) void qkv_gemm_kernel(
    const float* __restrict__ x, const float* __restrict__ w,
    const float* __restrict__ bias)
{
    __shared__ float As[2][8][128];
    __shared__ float Bs[2][8][128];

    const int tid = threadIdx.x;
    const int tx = tid & 15;        // 0..15 -> e sub-tile
    const int ty = tid >> 4;        // 0..15 -> m sub-tile
    const int m0 = blockIdx.y * 128;
    const int e0 = blockIdx.x * 128;

    // global -> smem loader mapping: 1 float4 per thread per operand per BK
    const int lrow = tid >> 1;        // 0..127
    const int lk   = (tid & 1) * 4;   // 0 or 4

    const float* aptr = x + (size_t)(m0 + lrow) * DIM_ + lk;
    const float* bptr = w + (size_t)(e0 + lrow) * DIM_ + lk;

    // preload tile 0
    {
        float4 a4 = *(const float4*)aptr;
        float4 b4 = *(const float4*)bptr;
        As[0][lk + 0][lrow] = a4.x; As[0][lk + 1][lrow] = a4.y;
        As[0][lk + 2][lrow] = a4.z; As[0][lk + 3][lrow] = a4.w;
        Bs[0][lk + 0][lrow] = b4.x; Bs[0][lk + 1][lrow] = b4.y;
        Bs[0][lk + 2][lrow] = b4.z; Bs[0][lk + 3][lrow] = b4.w;
    }
    __syncthreads();

    float acc[8][8];
    #pragma unroll
    for (int i = 0; i < 8; ++i)
        #pragma unroll
        for (int j = 0; j < 8; ++j) acc[i][j] = 0.f;

    int buf = 0;
    const int NT = DIM_ / 8;   // 128
    for (int t = 0; t < NT; ++t) {
        float4 na, nb;
        const bool more = (t + 1 < NT);
        if (more) {
            na = *(const float4*)(aptr + (t + 1) * 8);
            nb = *(const float4*)(bptr + (t + 1) * 8);
        }
        #pragma unroll
        for (int kk = 0; kk < 8; ++kk) {
            float4 af0 = *(const float4*)&As[buf][kk][ty * 8];
            float4 af1 = *(const float4*)&As[buf][kk][ty * 8 + 4];
            float4 bf0 = *(const float4*)&Bs[buf][kk][tx * 8];
            float4 bf1 = *(const float4*)&Bs[buf][kk][tx * 8 + 4];
            float a[8] = {af0.x, af0.y, af0.z, af0.w, af1.x, af1.y, af1.z, af1.w};
            float bb[8] = {bf0.x, bf0.y, bf0.z, bf0.w, bf1.x, bf1.y, bf1.z, bf1.w};
            #pragma unroll
            for (int i = 0; i < 8; ++i)
                #pragma unroll
                for (int j = 0; j < 8; ++j)
                    acc[i][j] = fmaf(a[i], bb[j], acc[i][j]);
        }
        if (more) {
            const int nb_i = buf ^ 1;
            As[nb_i][lk + 0][lrow] = na.x; As[nb_i][lk + 1][lrow] = na.y;
            As[nb_i][lk + 2][lrow] = na.z; As[nb_i][lk + 3][lrow] = na.w;
            Bs[nb_i][lk + 0][lrow] = nb.x; Bs[nb_i][lk + 1][lrow] = nb.y;
            Bs[nb_i][lk + 2][lrow] = nb.z; Bs[nb_i][lk + 3][lrow] = nb.w;
            __syncthreads();
            buf = nb_i;
        }
    }

    // bias + store
    float bv[8];
    #pragma unroll
    for (int j = 0; j < 8; ++j) bv[j] = bias[e0 + tx * 8 + j];

    #pragma unroll
    for (int i = 0; i < 8; ++i) {
        float* orow = g_qkv + (size_t)(m0 + ty * 8 + i) * QKV_STRIDE + e0 + tx * 8;
        float4 o0, o1;
        o0.x = acc[i][0] + bv[0]; o0.y = acc[i][1] + bv[1];
        o0.z = acc[i][2] + bv[2]; o0.w = acc[i][3] + bv[3];
        o1.x = acc[i][4] + bv[4]; o1.y = acc[i][5] + bv[5];
        o1.z = acc[i][6] + bv[6]; o1.w = acc[i][7] + bv[7];
        *(float4*)orow       = o0;
        *(float4*)(orow + 4) = o1;
    }
}

// ---------------------------------------------------------------------------
// Kernel 2: flash attention (fp32, full attention, online softmax).
// Block handles 64 queries of one (b,h). 64-key tiles. 256 threads.
// Thread (tx,ty) owns rows {ty+16i} x cols {tx+16j} (strided 4x4) -> conflict-
// free Ks reads with stride-65 smem rows.
// ---------------------------------------------------------------------------
__global__ __launch_bounds__(256) void attn_kernel(float* __restrict__ out)
{
    extern __shared__ float sm[];
    float* Qs = sm;              // [64][65]
    float* Ks = sm + 64 * 65;    // [64][65]
    float* Vs = sm + 2 * 64 * 65;
    float* Ss = sm + 3 * 64 * 65;

    const int tid = threadIdx.x;
    const int tx = tid & 15;
    const int ty = tid >> 4;
    const int bh = blockIdx.y;
    const int b  = bh >> 4;
    const int h  = bh & 15;
    const int q0 = blockIdx.x * 64;

    // ---- load Q tile (pre-scaled) ----
    {
        const int row = tid >> 2;          // 0..63
        const int d0  = (tid & 3) * 16;    // 0,16,32,48
        const float* src = g_qkv + (size_t)(b * N_ + q0 + row) * QKV_STRIDE + h * HD_ + d0;
        float* dst = Qs + row * 65 + d0;
        #pragma unroll
        for (int j = 0; j < 16; j += 4) {
            float4 v = *(const float4*)(src + j);
            dst[j + 0] = v.x * SCALE_; dst[j + 1] = v.y * SCALE_;
            dst[j + 2] = v.z * SCALE_; dst[j + 3] = v.w * SCALE_;
        }
    }

    float m_i[4], l_i[4], O[4][4];
    #pragma unroll
    for (int i = 0; i < 4; ++i) {
        m_i[i] = -CUDART_INF_F;
        l_i[i] = 0.f;
        #pragma unroll
        for (int j = 0; j < 4; ++j) O[i][j] = 0.f;
    }

    for (int kt = 0; kt < N_ / 64; ++kt) {
        // ---- load K, V tiles ----
        {
            const int row = tid >> 2;
            const int d0  = (tid & 3) * 16;
            const float* ksrc = g_qkv + (size_t)(b * N_ + kt * 64 + row) * QKV_STRIDE
                                + DIM_ + h * HD_ + d0;
            const float* vsrc = ksrc + DIM_;
            float* kdst = Ks + row * 65 + d0;
            float* vdst = Vs + row * 65 + d0;
            #pragma unroll
            for (int j = 0; j < 16; j += 4) {
                float4 kv = *(const float4*)(ksrc + j);
                float4 vv = *(const float4*)(vsrc + j);
                kdst[j + 0] = kv.x; kdst[j + 1] = kv.y;
                kdst[j + 2] = kv.z; kdst[j + 3] = kv.w;
                vdst[j + 0] = vv.x; vdst[j + 1] = vv.y;
                vdst[j + 2] = vv.z; vdst[j + 3] = vv.w;
            }
        }
        __syncthreads();

        // ---- S = Q @ K^T (scaled Q already) ----
        float acc[4][4];
        #pragma unroll
        for (int i = 0; i < 4; ++i)
            #pragma unroll
            for (int j = 0; j < 4; ++j) acc[i][j] = 0.f;

        #pragma unroll 4
        for (int k = 0; k < 64; ++k) {
            float a[4], bq[4];
            #pragma unroll
            for (int i = 0; i < 4; ++i) a[i]  = Qs[(ty + 16 * i) * 65 + k];
            #pragma unroll
            for (int j = 0; j < 4; ++j) bq[j] = Ks[(tx + 16 * j) * 65 + k];
            #pragma unroll
            for (int i = 0; i < 4; ++i)
                #pragma unroll
                for (int j = 0; j < 4; ++j)
                    acc[i][j] = fmaf(a[i], bq[j], acc[i][j]);
        }

        // ---- online softmax update (reduction across the 16 tx lanes) ----
        #pragma unroll
        for (int i = 0; i < 4; ++i) {
            float rm = fmaxf(fmaxf(acc[i][0], acc[i][1]), fmaxf(acc[i][2], acc[i][3]));
            #pragma unroll
            for (int mask = 1; mask < 16; mask <<= 1)
                rm = fmaxf(rm, __shfl_xor_sync(0xffffffffu, rm, mask));
            const float mnew = fmaxf(m_i[i], rm);
            const float corr = __expf(m_i[i] - mnew);
            float rs = 0.f;
            #pragma unroll
            for (int j = 0; j < 4; ++j) {
                float p = __expf(acc[i][j] - mnew);
                Ss[(ty + 16 * i) * 65 + tx + 16 * j] = p;
                rs += p;
            }
            #pragma unroll
            for (int mask = 1; mask < 16; mask <<= 1)
                rs += __shfl_xor_sync(0xffffffffu, rs, mask);
            l_i[i] = l_i[i] * corr + rs;
            m_i[i] = mnew;
            #pragma unroll
            for (int j = 0; j < 4; ++j) O[i][j] *= corr;
        }
        __syncthreads();

        // ---- O += P @ V ----
        #pragma unroll 4
        for (int k = 0; k < 64; ++k) {
            float p[4], v[4];
            #pragma unroll
            for (int i = 0; i < 4; ++i) p[i] = Ss[(ty + 16 * i) * 65 + k];
            #pragma unroll
            for (int j = 0; j < 4; ++j) v[j] = Vs[k * 65 + tx + 16 * j];
            #pragma unroll
            for (int i = 0; i < 4; ++i)
                #pragma unroll
                for (int j = 0; j < 4; ++j)
                    O[i][j] = fmaf(p[i], v[j], O[i][j]);
        }
        __syncthreads();
    }

    // ---- epilogue: normalize + write [B, N, H*HD] ----
    #pragma unroll
    for (int i = 0; i < 4; ++i) {
        const float inv = 1.f / l_i[i];
        float* orow = out + (size_t)(b * N_ + q0 + ty + 16 * i) * DIM_ + h * HD_;
        #pragma unroll
        for (int j = 0; j < 4; ++j)
            orow[tx + 16 * j] = O[i][j] * inv;
    }
}

// ---------------------------------------------------------------------------
extern "C" void kernel_launch(void* const* d_in, const int* in_sizes, int n_in,
                              void* d_out, int out_size)
{
    const float* x  = (const float*)d_in[0];
    const float* w  = (const float*)d_in[1];
    const float* bq = (const float*)d_in[2];
    float* out = (float*)d_out;

    // QKV projection: grid (3072/128, 8192/128) = (24, 64)
    dim3 g1(QKV_STRIDE / 128, (B_ * N_) / 128);
    qkv_gemm_kernel<<<g1, 256>>>(x, w, bq);

    // flash attention: grid (2048/64, B*H) = (32, 64)
    const int smem_bytes = 4 * 64 * 65 * 4;   // 66560
    cudaFuncSetAttribute(attn_kernel, cudaFuncAttributeMaxDynamicSharedMemorySize,
                         smem_bytes);
    dim3 g2(N_ / 64, B_ * H_);
    attn_kernel<<<g2, 256, smem_bytes>>>(out);
}

// round 3
// speedup vs baseline: 1.8406x; 1.8406x over previous
#include <cuda_runtime.h>
#include <math_constants.h>
#include <cstdint>

// Problem constants
#define B_   4
#define N_   2048
#define DIM_ 1024
#define H_   16
#define HD_  64
#define QKV_STRIDE 3072   // 3*DIM
#define SCALE_ 0.125f     // 1/sqrt(64)
#define PAD_ 68           // smem row pitch (floats): conflict-free frag reads

// Scratch for the QKV projection: [B*N, 3*DIM] = 8192 x 3072 fp32 = 96 MB.
__device__ float g_qkv[(size_t)B_ * N_ * QKV_STRIDE];

// ---------------------------------------------------------------------------
// helpers
// ---------------------------------------------------------------------------
__device__ __forceinline__ uint32_t f2tf32(float f) {
    uint32_t r;
    asm("cvt.rna.tf32.f32 %0, %1;" : "=r"(r) : "f"(f));
    return r;
}

__device__ __forceinline__ void mma_tf32(float* d, const uint32_t* a,
                                         uint32_t b0, uint32_t b1) {
    asm volatile(
        "mma.sync.aligned.m16n8k8.row.col.f32.tf32.tf32.f32 "
        "{%0,%1,%2,%3}, {%4,%5,%6,%7}, {%8,%9}, {%0,%1,%2,%3};\n"
        : "+f"(d[0]), "+f"(d[1]), "+f"(d[2]), "+f"(d[3])
        : "r"(a[0]), "r"(a[1]), "r"(a[2]), "r"(a[3]), "r"(b0), "r"(b1));
}

// ---------------------------------------------------------------------------
// Kernel 1: QKV projection.  C[m,e] = sum_k x[m,k] * w[e,k] + bias[e]
// M=8192, N=3072, K=1024.  128x128 block tile, BK=8, 256 threads, 8x8/thread.
// ---------------------------------------------------------------------------
__global__ __launch_bounds__(256) void qkv_gemm_kernel(
    const float* __restrict__ x, const float* __restrict__ w,
    const float* __restrict__ bias)
{
    __shared__ float As[2][8][128];
    __shared__ float Bs[2][8][128];

    const int tid = threadIdx.x;
    const int tx = tid & 15;
    const int ty = tid >> 4;
    const int m0 = blockIdx.y * 128;
    const int e0 = blockIdx.x * 128;

    const int lrow = tid >> 1;
    const int lk   = (tid & 1) * 4;

    const float* aptr = x + (size_t)(m0 + lrow) * DIM_ + lk;
    const float* bptr = w + (size_t)(e0 + lrow) * DIM_ + lk;

    {
        float4 a4 = *(const float4*)aptr;
        float4 b4 = *(const float4*)bptr;
        As[0][lk + 0][lrow] = a4.x; As[0][lk + 1][lrow] = a4.y;
        As[0][lk + 2][lrow] = a4.z; As[0][lk + 3][lrow] = a4.w;
        Bs[0][lk + 0][lrow] = b4.x; Bs[0][lk + 1][lrow] = b4.y;
        Bs[0][lk + 2][lrow] = b4.z; Bs[0][lk + 3][lrow] = b4.w;
    }
    __syncthreads();

    float acc[8][8];
    #pragma unroll
    for (int i = 0; i < 8; ++i)
        #pragma unroll
        for (int j = 0; j < 8; ++j) acc[i][j] = 0.f;

    int buf = 0;
    const int NT = DIM_ / 8;
    for (int t = 0; t < NT; ++t) {
        float4 na, nb;
        const bool more = (t + 1 < NT);
        if (more) {
            na = *(const float4*)(aptr + (t + 1) * 8);
            nb = *(const float4*)(bptr + (t + 1) * 8);
        }
        #pragma unroll
        for (int kk = 0; kk < 8; ++kk) {
            float4 af0 = *(const float4*)&As[buf][kk][ty * 8];
            float4 af1 = *(const float4*)&As[buf][kk][ty * 8 + 4];
            float4 bf0 = *(const float4*)&Bs[buf][kk][tx * 8];
            float4 bf1 = *(const float4*)&Bs[buf][kk][tx * 8 + 4];
            float a[8] = {af0.x, af0.y, af0.z, af0.w, af1.x, af1.y, af1.z, af1.w};
            float bb[8] = {bf0.x, bf0.y, bf0.z, bf0.w, bf1.x, bf1.y, bf1.z, bf1.w};
            #pragma unroll
            for (int i = 0; i < 8; ++i)
                #pragma unroll
                for (int j = 0; j < 8; ++j)
                    acc[i][j] = fmaf(a[i], bb[j], acc[i][j]);
        }
        if (more) {
            const int nb_i = buf ^ 1;
            As[nb_i][lk + 0][lrow] = na.x; As[nb_i][lk + 1][lrow] = na.y;
            As[nb_i][lk + 2][lrow] = na.z; As[nb_i][lk + 3][lrow] = na.w;
            Bs[nb_i][lk + 0][lrow] = nb.x; Bs[nb_i][lk + 1][lrow] = nb.y;
            Bs[nb_i][lk + 2][lrow] = nb.z; Bs[nb_i][lk + 3][lrow] = nb.w;
            __syncthreads();
            buf = nb_i;
        }
    }

    float bv[8];
    #pragma unroll
    for (int j = 0; j < 8; ++j) bv[j] = bias[e0 + tx * 8 + j];

    #pragma unroll
    for (int i = 0; i < 8; ++i) {
        float* orow = g_qkv + (size_t)(m0 + ty * 8 + i) * QKV_STRIDE + e0 + tx * 8;
        float4 o0, o1;
        o0.x = acc[i][0] + bv[0]; o0.y = acc[i][1] + bv[1];
        o0.z = acc[i][2] + bv[2]; o0.w = acc[i][3] + bv[3];
        o1.x = acc[i][4] + bv[4]; o1.y = acc[i][5] + bv[5];
        o1.z = acc[i][6] + bv[6]; o1.w = acc[i][7] + bv[7];
        *(float4*)orow       = o0;
        *(float4*)(orow + 4) = o1;
    }
}

// ---------------------------------------------------------------------------
// Kernel 2: flash attention on tensor cores (tf32 mma.sync, fp32 accumulate).
// Block: 128 queries of one (b,h), 8 warps (warp w -> q rows 16w..16w+15).
// Key tiles of 64.  Q fragments resident in registers; K/V/P staged in smem
// as pre-rounded tf32 bit patterns, row pitch PAD_=68 for conflict-free
// fragment gathers.  Online softmax in C-fragment registers.
// ---------------------------------------------------------------------------
__global__ __launch_bounds__(256, 2) void attn_tc_kernel(float* __restrict__ out)
{
    extern __shared__ uint32_t smu[];
    uint32_t* Qs = smu;                    // [128][PAD_]
    uint32_t* Ks = Qs + 128 * PAD_;        // [64][PAD_]
    uint32_t* Vs = Ks + 64 * PAD_;         // [64][PAD_]
    uint32_t* Ss = Vs + 64 * PAD_;         // [128][PAD_]

    const int tid  = threadIdx.x;
    const int lane = tid & 31;
    const int warp = tid >> 5;
    const int g    = lane >> 2;   // 0..7 : fragment row group
    const int t    = lane & 3;    // 0..3 : fragment col group
    const int bh = blockIdx.y;
    const int b  = bh >> 4;
    const int h  = bh & 15;
    const int q0 = blockIdx.x * 128;
    const int mrow = warp * 16;

    // ---- load Q tile (scaled, tf32-rounded) ----
    {
        const int row = tid >> 1;
        const int d0  = (tid & 1) * 32;
        const float* src = g_qkv + (size_t)(b * N_ + q0 + row) * QKV_STRIDE + h * HD_ + d0;
        uint32_t* dst = Qs + row * PAD_ + d0;
        #pragma unroll
        for (int j = 0; j < 32; j += 4) {
            float4 v = *(const float4*)(src + j);
            dst[j + 0] = f2tf32(v.x * SCALE_);
            dst[j + 1] = f2tf32(v.y * SCALE_);
            dst[j + 2] = f2tf32(v.z * SCALE_);
            dst[j + 3] = f2tf32(v.w * SCALE_);
        }
    }
    __syncthreads();

    // ---- Q fragments: 8 k-steps x 4 regs, resident all kernel ----
    uint32_t qa[8][4];
    #pragma unroll
    for (int ks = 0; ks < 8; ++ks) {
        const int k0 = ks * 8;
        qa[ks][0] = Qs[(mrow + g)     * PAD_ + k0 + t];
        qa[ks][1] = Qs[(mrow + g + 8) * PAD_ + k0 + t];
        qa[ks][2] = Qs[(mrow + g)     * PAD_ + k0 + t + 4];
        qa[ks][3] = Qs[(mrow + g + 8) * PAD_ + k0 + t + 4];
    }

    float m_[2] = {-CUDART_INF_F, -CUDART_INF_F};
    float l_[2] = {0.f, 0.f};
    float o[8][4];
    #pragma unroll
    for (int nt = 0; nt < 8; ++nt)
        #pragma unroll
        for (int c = 0; c < 4; ++c) o[nt][c] = 0.f;

    for (int kt = 0; kt < N_ / 64; ++kt) {
        __syncthreads();   // previous PV reads of Ks/Vs/Ss complete

        // ---- load K,V tile (tf32-rounded) ----
        {
            const int row = tid >> 2;
            const int d0  = (tid & 3) * 16;
            const float* ksrc = g_qkv + (size_t)(b * N_ + kt * 64 + row) * QKV_STRIDE
                                + DIM_ + h * HD_ + d0;
            const float* vsrc = ksrc + DIM_;
            uint32_t* kdst = Ks + row * PAD_ + d0;
            uint32_t* vdst = Vs + row * PAD_ + d0;
            #pragma unroll
            for (int j = 0; j < 16; j += 4) {
                float4 kv = *(const float4*)(ksrc + j);
                float4 vv = *(const float4*)(vsrc + j);
                kdst[j + 0] = f2tf32(kv.x); kdst[j + 1] = f2tf32(kv.y);
                kdst[j + 2] = f2tf32(kv.z); kdst[j + 3] = f2tf32(kv.w);
                vdst[j + 0] = f2tf32(vv.x); vdst[j + 1] = f2tf32(vv.y);
                vdst[j + 2] = f2tf32(vv.z); vdst[j + 3] = f2tf32(vv.w);
            }
        }
        __syncthreads();

        // ---- S = Q @ K^T : warp strip 16 x 64 ----
        float sacc[8][4];
        #pragma unroll
        for (int nt = 0; nt < 8; ++nt) {
            sacc[nt][0] = sacc[nt][1] = sacc[nt][2] = sacc[nt][3] = 0.f;
            const uint32_t* krow = Ks + (nt * 8 + g) * PAD_;
            #pragma unroll
            for (int ks = 0; ks < 8; ++ks) {
                uint32_t b0 = krow[ks * 8 + t];
                uint32_t b1 = krow[ks * 8 + t + 4];
                mma_tf32(sacc[nt], qa[ks], b0, b1);
            }
        }

        // ---- online softmax on fragments ----
        float mx0 = -CUDART_INF_F, mx1 = -CUDART_INF_F;
        #pragma unroll
        for (int nt = 0; nt < 8; ++nt) {
            mx0 = fmaxf(mx0, fmaxf(sacc[nt][0], sacc[nt][1]));
            mx1 = fmaxf(mx1, fmaxf(sacc[nt][2], sacc[nt][3]));
        }
        #pragma unroll
        for (int msk = 1; msk < 4; msk <<= 1) {
            mx0 = fmaxf(mx0, __shfl_xor_sync(0xffffffffu, mx0, msk));
            mx1 = fmaxf(mx1, __shfl_xor_sync(0xffffffffu, mx1, msk));
        }
        const float mn0 = fmaxf(m_[0], mx0);
        const float mn1 = fmaxf(m_[1], mx1);
        const float cr0 = __expf(m_[0] - mn0);
        const float cr1 = __expf(m_[1] - mn1);

        float rs0 = 0.f, rs1 = 0.f;
        uint32_t* prow0 = Ss + (mrow + g)     * PAD_ + 2 * t;
        uint32_t* prow1 = Ss + (mrow + g + 8) * PAD_ + 2 * t;
        #pragma unroll
        for (int nt = 0; nt < 8; ++nt) {
            float p0 = __expf(sacc[nt][0] - mn0);
            float p1 = __expf(sacc[nt][1] - mn0);
            float p2 = __expf(sacc[nt][2] - mn1);
            float p3 = __expf(sacc[nt][3] - mn1);
            rs0 += p0 + p1;
            rs1 += p2 + p3;
            prow0[nt * 8 + 0] = f2tf32(p0);
            prow0[nt * 8 + 1] = f2tf32(p1);
            prow1[nt * 8 + 0] = f2tf32(p2);
            prow1[nt * 8 + 1] = f2tf32(p3);
        }
        #pragma unroll
        for (int msk = 1; msk < 4; msk <<= 1) {
            rs0 += __shfl_xor_sync(0xffffffffu, rs0, msk);
            rs1 += __shfl_xor_sync(0xffffffffu, rs1, msk);
        }
        l_[0] = l_[0] * cr0 + rs0;
        l_[1] = l_[1] * cr1 + rs1;
        m_[0] = mn0; m_[1] = mn1;
        #pragma unroll
        for (int nt = 0; nt < 8; ++nt) {
            o[nt][0] *= cr0; o[nt][1] *= cr0;
            o[nt][2] *= cr1; o[nt][3] *= cr1;
        }
        __syncthreads();   // P visible to whole warp's fragment gathers

        // ---- O += P @ V ----
        #pragma unroll
        for (int ks = 0; ks < 8; ++ks) {
            uint32_t pa[4];
            pa[0] = Ss[(mrow + g)     * PAD_ + ks * 8 + t];
            pa[1] = Ss[(mrow + g + 8) * PAD_ + ks * 8 + t];
            pa[2] = Ss[(mrow + g)     * PAD_ + ks * 8 + t + 4];
            pa[3] = Ss[(mrow + g + 8) * PAD_ + ks * 8 + t + 4];
            const uint32_t* vrow0 = Vs + (ks * 8 + t)     * PAD_ + g;
            const uint32_t* vrow1 = Vs + (ks * 8 + t + 4) * PAD_ + g;
            #pragma unroll
            for (int nt = 0; nt < 8; ++nt) {
                uint32_t b0 = vrow0[nt * 8];
                uint32_t b1 = vrow1[nt * 8];
                mma_tf32(o[nt], pa, b0, b1);
            }
        }
    }

    // ---- epilogue: normalize + store ----
    const float inv0 = 1.f / l_[0];
    const float inv1 = 1.f / l_[1];
    const int r0 = q0 + mrow + g;
    float* po0 = out + (size_t)(b * N_ + r0) * DIM_ + h * HD_ + 2 * t;
    float* po1 = po0 + (size_t)8 * DIM_;
    #pragma unroll
    for (int nt = 0; nt < 8; ++nt) {
        float2 v0 = make_float2(o[nt][0] * inv0, o[nt][1] * inv0);
        float2 v1 = make_float2(o[nt][2] * inv1, o[nt][3] * inv1);
        *(float2*)(po0 + nt * 8) = v0;
        *(float2*)(po1 + nt * 8) = v1;
    }
}

// ---------------------------------------------------------------------------
extern "C" void kernel_launch(void* const* d_in, const int* in_sizes, int n_in,
                              void* d_out, int out_size)
{
    const float* x  = (const float*)d_in[0];
    const float* w  = (const float*)d_in[1];
    const float* bq = (const float*)d_in[2];
    float* out = (float*)d_out;

    dim3 g1(QKV_STRIDE / 128, (B_ * N_) / 128);
    qkv_gemm_kernel<<<g1, 256>>>(x, w, bq);

    static bool attr_set = false;
    const int smem_bytes = (128 * PAD_ + 64 * PAD_ + 64 * PAD_ + 128 * PAD_) * 4;
    if (!attr_set) {
        cudaFuncSetAttribute(attn_tc_kernel,
                             cudaFuncAttributeMaxDynamicSharedMemorySize, smem_bytes);
        attr_set = true;
    }
    dim3 g2(N_ / 128, B_ * H_);
    attn_tc_kernel<<<g2, 256, smem_bytes>>>(out);
}